// round 12
// baseline (speedup 1.0000x reference)
#include <cuda_runtime.h>
#include <math.h>

// C=6, N=5 modes, LAYERS=4, OUTPUT=2, B=2048
#define DIM 7776            // 6^5
#define BD  256
typedef unsigned long long ull;

// Half-layer gate storage (plain complex float2):
//   10 BS gates x 164 (sector rows padded to even length) = 1640
//   5 one-mode gates x 36 (squeeze compacted to 24 used)  = 180
#define HLF2 1820
#define HLF4 910

// ---------------- persistent device scratch ----------------
__device__ __align__(16) float2 g_all[8 * HLF2];   // all gates, execution order
__device__ float g_init[2048 * 5 * 6];

__constant__ float SQT[5] = {1.0f, 1.41421356237f, 1.73205080757f, 2.0f, 2.2360679775f};

// ---------------- helpers ----------------
__device__ __forceinline__ float2 cmul(float2 a, float2 b) {
    return make_float2(a.x * b.x - a.y * b.y, a.x * b.y + a.y * b.x);
}
__device__ __forceinline__ float2 cmadd(float2 a, float2 b, float2 c) {
    c.x = fmaf(a.x, b.x, fmaf(-a.y, b.y, c.x));
    c.y = fmaf(a.x, b.y, fmaf(a.y, b.x, c.y));
    return c;
}
__device__ __forceinline__ void ffma2(ull& d, ull a, ull b) {
    asm("fma.rn.f32x2 %0, %1, %2, %0;" : "+l"(d) : "l"(a), "l"(b));
}
// from packed complex v=(re,im) build dR=(re,re), dI=(im,im)
__device__ __forceinline__ void dupRI(ull v, ull& dR, ull& dI) {
    unsigned lo, hi;
    asm("mov.b64 {%0,%1}, %2;" : "=r"(lo), "=r"(hi) : "l"(v));
    asm("mov.b64 %0, {%1,%1};" : "=l"(dR) : "r"(lo));
    asm("mov.b64 %0, {%1,%1};" : "=l"(dI) : "r"(hi));
}

// ---------------- banded 6x6 expm (registers), bands at +-D, pre-scaled 1/64 ----
template <int D>
__device__ void expm_banded(const float2* lo, const float2* hi, float2* R) {
    float2 T[36];
#pragma unroll
    for (int i = 0; i < 36; i++) R[i] = make_float2(((i % 6) == (i / 6)) ? 1.f : 0.f, 0.f);
#pragma unroll 1
    for (int k = 16; k >= 1; k--) {
#pragma unroll
        for (int i = 0; i < 6; i++) {
#pragma unroll
            for (int j = 0; j < 6; j++) {
                float2 acc = make_float2(0.f, 0.f);
                if (i >= D)    acc = cmadd(lo[i], R[(i - D) * 6 + j], acc);
                if (i + D < 6) acc = cmadd(hi[i], R[(i + D) * 6 + j], acc);
                T[i * 6 + j] = acc;
            }
        }
        float inv = 1.f / (float)k;
#pragma unroll
        for (int i = 0; i < 36; i++) {
            float d = ((i % 6) == (i / 6)) ? 1.f : 0.f;
            R[i] = make_float2(fmaf(T[i].x, inv, d), T[i].y * inv);
        }
    }
#pragma unroll 1
    for (int s = 0; s < 6; s++) {
#pragma unroll
        for (int i = 0; i < 6; i++)
#pragma unroll
            for (int j = 0; j < 6; j++) {
                float2 acc = make_float2(0.f, 0.f);
#pragma unroll
                for (int kk = 0; kk < 6; kk++) acc = cmadd(R[i * 6 + kk], R[kk * 6 + j], acc);
                T[i * 6 + j] = acc;
            }
#pragma unroll
        for (int i = 0; i < 36; i++) R[i] = T[i];
    }
}

// ---------------- dummy kernel (ncu launch-index alignment) ----------------
__global__ void noop_kernel() {}

// ---------------- S1: initial columns + 6x6 gates (rot + kerr folded) ----------
__global__ void s1_kernel(const float* __restrict__ x, const float* __restrict__ lin,
                          const float* __restrict__ act, const float* __restrict__ lact,
                          int B) {
    int idx = blockIdx.x * blockDim.x + threadIdx.x;
    int nInit = B * 5;
    const float sc = 1.f / 64.f;
    float2 lo[6], hi[6], R[36];
    if (idx < nInit) {
        float r = x[idx];   // disp(r, 0)
#pragma unroll
        for (int n = 0; n < 6; n++) {
            lo[n] = make_float2(r * sqrtf((float)n) * sc, 0.f);
            hi[n] = make_float2(-r * sqrtf((float)(n + 1)) * sc, 0.f);
        }
        expm_banded<1>(lo, hi, R);
#pragma unroll
        for (int n = 0; n < 6; n++) g_init[idx * 6 + n] = R[n * 6].x;  // column 0 (real)
    } else if (idx < nInit + 40) {
        int k = idx - nInit;
        int isDp = (k >= 20);
        int k2 = isDp ? k - 20 : k;
        int l = k2 / 5, i = k2 - 5 * l;
        float rphi;
        if (!isDp) {
            float r = lin[l * 63 + 24 + i];
#pragma unroll
            for (int n = 0; n < 6; n++) {
                lo[n] = make_float2(-0.5f * r * sqrtf((float)(n * (n - 1))) * sc, 0.f);
                hi[n] = make_float2( 0.5f * r * sqrtf((float)((n + 1) * (n + 2))) * sc, 0.f);
            }
            expm_banded<2>(lo, hi, R);
            rphi = (i < 4) ? lin[l * 63 + 20 + i] : 0.f;   // interferometer A rot
        } else {
            float dr = lin[l * 63 + 53 + i];
            float dp = lin[l * 63 + 58 + i];
            float sp, cp; sincosf(dp, &sp, &cp);
#pragma unroll
            for (int n = 0; n < 6; n++) {
                float sn = sqrtf((float)n) * sc, sn1 = sqrtf((float)(n + 1)) * sc;
                lo[n] = make_float2(dr * cp * sn, dr * sp * sn);
                hi[n] = make_float2(-dr * cp * sn1, dr * sp * sn1);
            }
            expm_banded<1>(lo, hi, R);
            rphi = (i < 4) ? lin[l * 63 + 49 + i] : 0.f;   // interferometer B rot
        }
        // fold rotation diagonal: column j *= e^{i rphi j}
#pragma unroll
        for (int c = 0; c < 6; c++) {
            float s2, c2; sincosf(rphi * (float)c, &s2, &c2);
            float2 ph = make_float2(c2, s2);
#pragma unroll
            for (int rr = 0; rr < 6; rr++) R[rr * 6 + c] = cmul(R[rr * 6 + c], ph);
        }
        if (isDp) {
            // fold kerr diagonal (applied right after disp on same mode): row r *= e^{i kv r^2}
            float kv = (l < 3) ? act[l * 5 + i] : ((i < 2) ? lact[i] : 0.f);
#pragma unroll
            for (int rr = 0; rr < 6; rr++) {
                float s2, c2; sincosf(kv * (float)(rr * rr), &s2, &c2);
                float2 ph = make_float2(c2, s2);
#pragma unroll
                for (int c = 0; c < 6; c++) R[rr * 6 + c] = cmul(ph, R[rr * 6 + c]);
            }
        }
        int hl = 2 * l + (isDp ? 1 : 0);
        float2* dst = g_all + hl * HLF2 + 1640 + i * 36;
        if (!isDp) {
            // squeeze: compact parity-sparse rows: row p holds q = (p&1)+2j, j=0..2, + pad
#pragma unroll
            for (int p = 0; p < 6; p++) {
#pragma unroll
                for (int j = 0; j < 3; j++) dst[p * 4 + j] = R[p * 6 + (p & 1) + 2 * j];
                dst[p * 4 + 3] = make_float2(0.f, 0.f);
            }
        } else {
#pragma unroll
            for (int e = 0; e < 36; e++) dst[e] = R[e];
        }
    }
}

// ---------------- S2: 80 beam-splitter 36x36 expm's, padded block extraction ----
__global__ void s2_kernel(const float* __restrict__ lin) {
    __shared__ float2 Rb[1296], Tb[1296];
    __shared__ float2 h1[36], h2[36];
    __shared__ int r1[36], r2[36];
    int gid = blockIdx.x;          // hl*10 + g
    int l = gid / 20, rem = gid % 20, half = rem / 10, g = rem % 10;
    const float* p = lin + l * 63 + (half ? 29 : 0);
    float theta = p[g], phi = p[10 + g];
    float sp, cp; sincosf(phi, &sp, &cp);
    int tid = threadIdx.x;
    if (tid < 36) {
        int i1 = tid / 6, i2 = tid % 6;
        if (i1 + 1 < 6 && i2 - 1 >= 0) {
            float v = theta * sqrtf((float)((i1 + 1) * i2)) * (1.f / 64.f);
            h1[tid] = make_float2(v * cp, v * sp); r1[tid] = (i1 + 1) * 6 + (i2 - 1);
        } else { h1[tid] = make_float2(0.f, 0.f); r1[tid] = tid; }
        if (i1 - 1 >= 0 && i2 + 1 < 6) {
            float v = theta * sqrtf((float)(i1 * (i2 + 1))) * (1.f / 64.f);
            h2[tid] = make_float2(-v * cp, v * sp); r2[tid] = (i1 - 1) * 6 + (i2 + 1);
        } else { h2[tid] = make_float2(0.f, 0.f); r2[tid] = tid; }
    }
    for (int e = tid; e < 1296; e += blockDim.x) {
        int row = e / 36, col = e % 36;
        Rb[e] = make_float2((row == col) ? 1.f : 0.f, 0.f);
    }
    __syncthreads();
    for (int k = 16; k >= 1; k--) {
        for (int e = tid; e < 1296; e += blockDim.x) {
            int row = e / 36, col = e % 36;
            float2 acc = make_float2(0.f, 0.f);
            acc = cmadd(h1[row], Rb[r1[row] * 36 + col], acc);
            acc = cmadd(h2[row], Rb[r2[row] * 36 + col], acc);
            Tb[e] = acc;
        }
        __syncthreads();
        float inv = 1.f / (float)k;
        for (int e = tid; e < 1296; e += blockDim.x) {
            int row = e / 36, col = e % 36;
            float d = (row == col) ? 1.f : 0.f;
            Rb[e] = make_float2(fmaf(Tb[e].x, inv, d), Tb[e].y * inv);
        }
        __syncthreads();
    }
    float2* cur = Rb; float2* nxt = Tb;
    for (int s = 0; s < 6; s++) {
        for (int e = tid; e < 1296; e += blockDim.x) {
            int row = e / 36, col = e % 36;
            float2 acc = make_float2(0.f, 0.f);
#pragma unroll
            for (int kk = 0; kk < 36; kk++)
                acc = cmadd(cur[row * 36 + kk], cur[kk * 36 + col], acc);
            nxt[e] = acc;
        }
        __syncthreads();
        float2* t = cur; cur = nxt; nxt = t;
    }
    // write block-diagonal entries in padded-even-row layout (164 slots/gate)
    int hl = gid / 10, gg = gid % 10;
    for (int slot = tid; slot < 164; slot += blockDim.x) {
        int off = 0, s = 0, bsz = 1, bszP = 2;
        for (s = 0; s < 11; s++) {
            bsz = (s < 6) ? s + 1 : 11 - s;
            bszP = (bsz + 1) & ~1;
            if (slot < off + bsz * bszP) break;
            off += bsz * bszP;
        }
        int local = slot - off;
        int r = local / bszP, c = local % bszP;
        float2 v = make_float2(0.f, 0.f);
        if (c < bsz) {
            int lo = (s < 6) ? 0 : s - 5;
            int rj = (lo + r) * 6 + (s - lo - r);
            int cj = (lo + c) * 6 + (s - lo - c);
            v = cur[rj * 36 + cj];
        }
        g_all[hl * HLF2 + gg * 164 + slot] = v;
    }
}

// ---------------- BS apply: single fiber per thread (R9 shape) -----------------
template <int K>
__device__ __forceinline__ void apply_bs_T(const float2* __restrict__ Uf, float2* st, int tid) {
    constexpr int SPv[5] = {1296, 216, 36, 6, 1};
    constexpr int SA = SPv[K], SB = SPv[K + 1];
    constexpr int sm0 = (K == 0) ? 2 : 0;
    constexpr int sm1 = (K <= 1) ? 3 : 1;
    constexpr int sm2 = (K <= 2) ? 4 : 2;
    constexpr int om0 = SPv[sm0], om1 = SPv[sm1], om2 = SPv[sm2];
    if (tid >= 216) return;
    int d0 = tid % 6, t1 = tid / 6;
    int d1 = t1 % 6, d2 = t1 / 6;
    int base = d0 * om2 + d1 * om1 + d2 * om0;
    const ull* sp = (const ull*)st;
    const ulonglong2* Up = (const ulonglong2*)Uf;
    constexpr int secF4[11] = {0, 1, 3, 9, 17, 32, 50, 65, 73, 79, 81};
#pragma unroll
    for (int s = 0; s < 11; s++) {
        const int bsz = (s < 6) ? s + 1 : 11 - s;
        const int lo = (s < 6) ? 0 : s - 5;
        const int bszP2 = (bsz + 1) / 2;          // float4 per row
        ull dR[6], dI[6];
#pragma unroll
        for (int c = 0; c < bsz; c++) {
            ull v = sp[base + (lo + c) * SA + (s - lo - c) * SB];
            dupRI(v, dR[c], dI[c]);
        }
        if (bsz & 1) { dR[bsz] = 0; dI[bsz] = 0; }   // pad slot (coeff stored 0)
#pragma unroll
        for (int r = 0; r < bsz; r++) {
            ull S1 = 0, S2 = 0;
#pragma unroll
            for (int cp = 0; cp < bszP2; cp++) {
                ulonglong2 gg = Up[secF4[s] + r * bszP2 + cp];
                ffma2(S1, gg.x, dR[2 * cp]);     ffma2(S2, gg.x, dI[2 * cp]);
                ffma2(S1, gg.y, dR[2 * cp + 1]); ffma2(S2, gg.y, dI[2 * cp + 1]);
            }
            float2 f1 = *(float2*)&S1;
            float2 f2 = *(float2*)&S2;
            st[base + (lo + r) * SA + (s - lo - r) * SB] = make_float2(f1.x - f2.y, f1.y + f2.x);
        }
    }
}

// ---------------- 1-mode apply: coeffs hoisted to registers once per gate ------
template <int M, bool SQ>
__device__ __forceinline__ void apply_1m_T(const float2* __restrict__ Uf, float2* st, int tid) {
    constexpr int SPv[5] = {1296, 216, 36, 6, 1};
    constexpr int SM = SPv[M];
    constexpr int a0 = (M == 0) ? 1 : 0;
    constexpr int a1 = (M <= 1) ? 2 : 1;
    constexpr int a2 = (M <= 2) ? 3 : 2;
    constexpr int a3 = (M <= 3) ? 4 : 3;
    constexpr int om0 = SPv[a0], om1 = SPv[a1], om2 = SPv[a2], om3 = SPv[a3];
    const ulonglong2* __restrict__ Up = (const ulonglong2*)Uf;
    constexpr int NG = SQ ? 12 : 18;
    ulonglong2 g[NG];
#pragma unroll
    for (int i = 0; i < NG; i++) g[i] = Up[i];     // once per gate, not per fiber
    for (int f = tid; f < 1296; f += BD) {
        int e0 = f % 6, t = f / 6;
        int e1 = t % 6; t /= 6;
        int e2 = t % 6; int e3 = t / 6;
        int base = e0 * om3 + e1 * om2 + e2 * om1 + e3 * om0;
        const ull* sp = (const ull*)st;
        ull dR[6], dI[6];
#pragma unroll
        for (int q = 0; q < 6; q++) dupRI(sp[base + q * SM], dR[q], dI[q]);
#pragma unroll
        for (int p = 0; p < 6; p++) {
            ull S1 = 0, S2 = 0;
            if (SQ) {           // compact parity rows: q = (p&1)+2j, j<3 (pad dropped)
                const int q0 = p & 1;
                ulonglong2 g0 = g[p * 2 + 0];
                ulonglong2 g1 = g[p * 2 + 1];
                ffma2(S1, g0.x, dR[q0]);     ffma2(S2, g0.x, dI[q0]);
                ffma2(S1, g0.y, dR[q0 + 2]); ffma2(S2, g0.y, dI[q0 + 2]);
                ffma2(S1, g1.x, dR[q0 + 4]); ffma2(S2, g1.x, dI[q0 + 4]);
            } else {
#pragma unroll
                for (int cp = 0; cp < 3; cp++) {
                    ulonglong2 gg = g[p * 3 + cp];
                    ffma2(S1, gg.x, dR[2 * cp]);     ffma2(S2, gg.x, dI[2 * cp]);
                    ffma2(S1, gg.y, dR[2 * cp + 1]); ffma2(S2, gg.y, dI[2 * cp + 1]);
                }
            }
            float2 f1 = *(float2*)&S1;
            float2 f2 = *(float2*)&S2;
            st[base + p * SM] = make_float2(f1.x - f2.y, f1.y + f2.x);
        }
    }
}

// ---------------- main kernel: one CTA per batch element, occ 2 ---------------
__global__ void __launch_bounds__(BD, 2) qdn_main(float* __restrict__ out) {
    extern __shared__ __align__(16) char smraw[];
    float2* Ustage = (float2*)smraw;                        // 14560 B
    float2* st = (float2*)(smraw + HLF2 * sizeof(float2));  // 62208 B
    __shared__ float ct[30];
    __shared__ float red[16];

    int b = blockIdx.x;
    int tid = threadIdx.x;

    // ---- initial product state (real) ----
    if (tid < 30) ct[tid] = g_init[(b * 5 + tid / 6) * 6 + (tid % 6)];
    __syncthreads();
    for (int idx = tid; idx < DIM; idx += BD) {
        int t = idx;
        int d4 = t % 6; t /= 6; int d3 = t % 6; t /= 6; int d2 = t % 6; t /= 6;
        int d1 = t % 6; int d0 = t / 6;
        float v = ct[d0] * ct[6 + d1] * ct[12 + d2] * ct[18 + d3] * ct[24 + d4];
        st[idx] = make_float2(v, 0.f);
    }
    __syncthreads();

    for (int l = 0; l < 4; l++) {
        for (int half = 0; half < 2; half++) {
            // stage this half-layer's gates (float4 bulk copy)
            const float4* srcU = (const float4*)(g_all + (l * 2 + half) * HLF2);
            float4* dstU = (float4*)Ustage;
            for (int i = tid; i < HLF4; i += BD) dstU[i] = srcU[i];
            __syncthreads();
            // BS gate mode sequence: 0,2,1,3,0,2,1,3,0,2
            apply_bs_T<0>(Ustage + 0 * 164, st, tid); __syncthreads();
            apply_bs_T<2>(Ustage + 1 * 164, st, tid); __syncthreads();
            apply_bs_T<1>(Ustage + 2 * 164, st, tid); __syncthreads();
            apply_bs_T<3>(Ustage + 3 * 164, st, tid); __syncthreads();
            apply_bs_T<0>(Ustage + 4 * 164, st, tid); __syncthreads();
            apply_bs_T<2>(Ustage + 5 * 164, st, tid); __syncthreads();
            apply_bs_T<1>(Ustage + 6 * 164, st, tid); __syncthreads();
            apply_bs_T<3>(Ustage + 7 * 164, st, tid); __syncthreads();
            apply_bs_T<0>(Ustage + 8 * 164, st, tid); __syncthreads();
            apply_bs_T<2>(Ustage + 9 * 164, st, tid); __syncthreads();
            const float2* mg = Ustage + 1640;
            if (half == 0) {   // squeeze gates: compact parity rows
                apply_1m_T<0, true>(mg + 0 * 36, st, tid); __syncthreads();
                apply_1m_T<1, true>(mg + 1 * 36, st, tid); __syncthreads();
                apply_1m_T<2, true>(mg + 2 * 36, st, tid); __syncthreads();
                apply_1m_T<3, true>(mg + 3 * 36, st, tid); __syncthreads();
                apply_1m_T<4, true>(mg + 4 * 36, st, tid); __syncthreads();
            } else {           // displacement gates (rot+kerr folded): dense
                apply_1m_T<0, false>(mg + 0 * 36, st, tid); __syncthreads();
                apply_1m_T<1, false>(mg + 1 * 36, st, tid); __syncthreads();
                apply_1m_T<2, false>(mg + 2 * 36, st, tid); __syncthreads();
                apply_1m_T<3, false>(mg + 3 * 36, st, tid); __syncthreads();
                apply_1m_T<4, false>(mg + 4 * 36, st, tid); __syncthreads();
            }
        }
    }

    // ---- expectations <X_0>, <X_1> ----
    float acc0 = 0.f, acc1 = 0.f;
    for (int idx = tid; idx < DIM; idx += BD) {
        int d0 = idx / 1296;
        int d1 = (idx / 216) % 6;
        float2 a = st[idx];
        if (d0 < 5) {
            float2 bb = st[idx + 1296];
            acc0 = fmaf(SQT[d0], a.x * bb.x + a.y * bb.y, acc0);
        }
        if (d1 < 5) {
            float2 bb = st[idx + 216];
            acc1 = fmaf(SQT[d1], a.x * bb.x + a.y * bb.y, acc1);
        }
    }
#pragma unroll
    for (int off = 16; off > 0; off >>= 1) {
        acc0 += __shfl_down_sync(0xffffffffu, acc0, off);
        acc1 += __shfl_down_sync(0xffffffffu, acc1, off);
    }
    int w = tid >> 5, lane = tid & 31;
    if (lane == 0) { red[w] = acc0; red[8 + w] = acc1; }
    __syncthreads();
    if (tid == 0) {
        float s0 = 0.f, s1 = 0.f;
        for (int ww = 0; ww < 8; ww++) { s0 += red[ww]; s1 += red[8 + ww]; }
        out[b * 2 + 0] = 2.f * s0;
        out[b * 2 + 1] = 2.f * s1;
    }
}

// ---------------- launch ----------------
extern "C" void kernel_launch(void* const* d_in, const int* in_sizes, int n_in,
                              void* d_out, int out_size) {
    const float* x    = (const float*)d_in[0];
    const float* lin  = (const float*)d_in[1];
    const float* act  = (const float*)d_in[2];
    const float* lact = (const float*)d_in[3];
    float* out = (float*)d_out;
    int B = in_sizes[0] / 5;

    size_t shm = HLF2 * sizeof(float2) + (size_t)DIM * sizeof(float2);   // 76768 B
    cudaFuncSetAttribute(qdn_main, cudaFuncAttributeMaxDynamicSharedMemorySize, (int)shm);

    int n1 = B * 5 + 40;
    noop_kernel<<<1, 32>>>();
    s1_kernel<<<(n1 + 255) / 256, 256>>>(x, lin, act, lact, B);
    s2_kernel<<<80, 256>>>(lin);
    qdn_main<<<B, BD, shm>>>(out);
}

// round 14
// speedup vs baseline: 1.7731x; 1.7731x over previous
#include <cuda_runtime.h>
#include <math.h>

// C=6, N=5 modes, LAYERS=4, OUTPUT=2, B=2048
#define DIM 7776            // 6^5
#define BD  256
typedef unsigned long long ull;

// Half-layer gate storage (plain complex float2):
//   10 BS gates x 164 (sector rows padded to even length) = 1640
//   5 one-mode gates x 36 (squeeze compacted to 24 used)  = 180
#define HLF2 1820
#define HLF4 910

// padded state strides (float2 = 8B units); residues mod 16: 4,6,4,6,1
#define P0 1380
#define P1 230
#define P2 36
#define P3 6
#define P4 1
#define STATEF2 (6 * P0)    // 8280 float2 = 66240 B

// ---------------- persistent device scratch ----------------
__device__ __align__(16) float2 g_all[8 * HLF2];   // all gates, execution order
__device__ float g_init[2048 * 5 * 6];

__constant__ float SQT[5] = {1.0f, 1.41421356237f, 1.73205080757f, 2.0f, 2.2360679775f};

// ---------------- helpers ----------------
__device__ __forceinline__ float2 cmul(float2 a, float2 b) {
    return make_float2(a.x * b.x - a.y * b.y, a.x * b.y + a.y * b.x);
}
__device__ __forceinline__ float2 cmadd(float2 a, float2 b, float2 c) {
    c.x = fmaf(a.x, b.x, fmaf(-a.y, b.y, c.x));
    c.y = fmaf(a.x, b.y, fmaf(a.y, b.x, c.y));
    return c;
}
__device__ __forceinline__ void ffma2(ull& d, ull a, ull b) {
    asm("fma.rn.f32x2 %0, %1, %2, %0;" : "+l"(d) : "l"(a), "l"(b));
}
// from packed complex v=(re,im) build dR=(re,re), dI=(im,im)
__device__ __forceinline__ void dupRI(ull v, ull& dR, ull& dI) {
    unsigned lo, hi;
    asm("mov.b64 {%0,%1}, %2;" : "=r"(lo), "=r"(hi) : "l"(v));
    asm("mov.b64 %0, {%1,%1};" : "=l"(dR) : "r"(lo));
    asm("mov.b64 %0, {%1,%1};" : "=l"(dI) : "r"(hi));
}
__device__ __forceinline__ void dup2f(float re, float im, ull& dR, ull& dI) {
    unsigned lo = __float_as_uint(re), hi = __float_as_uint(im);
    asm("mov.b64 %0, {%1,%1};" : "=l"(dR) : "r"(lo));
    asm("mov.b64 %0, {%1,%1};" : "=l"(dI) : "r"(hi));
}

// ---------------- banded 6x6 expm (registers), bands at +-D, pre-scaled 1/64 ----
template <int D>
__device__ void expm_banded(const float2* lo, const float2* hi, float2* R) {
    float2 T[36];
#pragma unroll
    for (int i = 0; i < 36; i++) R[i] = make_float2(((i % 6) == (i / 6)) ? 1.f : 0.f, 0.f);
#pragma unroll 1
    for (int k = 16; k >= 1; k--) {
#pragma unroll
        for (int i = 0; i < 6; i++) {
#pragma unroll
            for (int j = 0; j < 6; j++) {
                float2 acc = make_float2(0.f, 0.f);
                if (i >= D)    acc = cmadd(lo[i], R[(i - D) * 6 + j], acc);
                if (i + D < 6) acc = cmadd(hi[i], R[(i + D) * 6 + j], acc);
                T[i * 6 + j] = acc;
            }
        }
        float inv = 1.f / (float)k;
#pragma unroll
        for (int i = 0; i < 36; i++) {
            float d = ((i % 6) == (i / 6)) ? 1.f : 0.f;
            R[i] = make_float2(fmaf(T[i].x, inv, d), T[i].y * inv);
        }
    }
#pragma unroll 1
    for (int s = 0; s < 6; s++) {
#pragma unroll
        for (int i = 0; i < 6; i++)
#pragma unroll
            for (int j = 0; j < 6; j++) {
                float2 acc = make_float2(0.f, 0.f);
#pragma unroll
                for (int kk = 0; kk < 6; kk++) acc = cmadd(R[i * 6 + kk], R[kk * 6 + j], acc);
                T[i * 6 + j] = acc;
            }
#pragma unroll
        for (int i = 0; i < 36; i++) R[i] = T[i];
    }
}

// ---------------- dummy kernel (ncu launch-index alignment) ----------------
__global__ void noop_kernel() {}

// ---------------- S1: initial columns + 6x6 gates (rot + kerr folded) ----------
__global__ void s1_kernel(const float* __restrict__ x, const float* __restrict__ lin,
                          const float* __restrict__ act, const float* __restrict__ lact,
                          int B) {
    int idx = blockIdx.x * blockDim.x + threadIdx.x;
    int nInit = B * 5;
    const float sc = 1.f / 64.f;
    float2 lo[6], hi[6], R[36];
    if (idx < nInit) {
        float r = x[idx];   // disp(r, 0)
#pragma unroll
        for (int n = 0; n < 6; n++) {
            lo[n] = make_float2(r * sqrtf((float)n) * sc, 0.f);
            hi[n] = make_float2(-r * sqrtf((float)(n + 1)) * sc, 0.f);
        }
        expm_banded<1>(lo, hi, R);
#pragma unroll
        for (int n = 0; n < 6; n++) g_init[idx * 6 + n] = R[n * 6].x;  // column 0 (real)
    } else if (idx < nInit + 40) {
        int k = idx - nInit;
        int isDp = (k >= 20);
        int k2 = isDp ? k - 20 : k;
        int l = k2 / 5, i = k2 - 5 * l;
        float rphi;
        if (!isDp) {
            float r = lin[l * 63 + 24 + i];
#pragma unroll
            for (int n = 0; n < 6; n++) {
                lo[n] = make_float2(-0.5f * r * sqrtf((float)(n * (n - 1))) * sc, 0.f);
                hi[n] = make_float2( 0.5f * r * sqrtf((float)((n + 1) * (n + 2))) * sc, 0.f);
            }
            expm_banded<2>(lo, hi, R);
            rphi = (i < 4) ? lin[l * 63 + 20 + i] : 0.f;   // interferometer A rot
        } else {
            float dr = lin[l * 63 + 53 + i];
            float dp = lin[l * 63 + 58 + i];
            float sp, cp; sincosf(dp, &sp, &cp);
#pragma unroll
            for (int n = 0; n < 6; n++) {
                float sn = sqrtf((float)n) * sc, sn1 = sqrtf((float)(n + 1)) * sc;
                lo[n] = make_float2(dr * cp * sn, dr * sp * sn);
                hi[n] = make_float2(-dr * cp * sn1, dr * sp * sn1);
            }
            expm_banded<1>(lo, hi, R);
            rphi = (i < 4) ? lin[l * 63 + 49 + i] : 0.f;   // interferometer B rot
        }
        // fold rotation diagonal: column j *= e^{i rphi j}
#pragma unroll
        for (int c = 0; c < 6; c++) {
            float s2, c2; sincosf(rphi * (float)c, &s2, &c2);
            float2 ph = make_float2(c2, s2);
#pragma unroll
            for (int rr = 0; rr < 6; rr++) R[rr * 6 + c] = cmul(R[rr * 6 + c], ph);
        }
        if (isDp) {
            // fold kerr diagonal (applied right after disp on same mode): row r *= e^{i kv r^2}
            float kv = (l < 3) ? act[l * 5 + i] : ((i < 2) ? lact[i] : 0.f);
#pragma unroll
            for (int rr = 0; rr < 6; rr++) {
                float s2, c2; sincosf(kv * (float)(rr * rr), &s2, &c2);
                float2 ph = make_float2(c2, s2);
#pragma unroll
                for (int c = 0; c < 6; c++) R[rr * 6 + c] = cmul(ph, R[rr * 6 + c]);
            }
        }
        int hl = 2 * l + (isDp ? 1 : 0);
        float2* dst = g_all + hl * HLF2 + 1640 + i * 36;
        if (!isDp) {
            // squeeze: compact parity-sparse rows: row p holds q = (p&1)+2j, j=0..2, + pad
#pragma unroll
            for (int p = 0; p < 6; p++) {
#pragma unroll
                for (int j = 0; j < 3; j++) dst[p * 4 + j] = R[p * 6 + (p & 1) + 2 * j];
                dst[p * 4 + 3] = make_float2(0.f, 0.f);
            }
        } else {
#pragma unroll
            for (int e = 0; e < 36; e++) dst[e] = R[e];
        }
    }
}

// ---------------- S2: 80 beam-splitter 36x36 expm's, padded block extraction ----
__global__ void s2_kernel(const float* __restrict__ lin) {
    __shared__ float2 Rb[1296], Tb[1296];
    __shared__ float2 h1[36], h2[36];
    __shared__ int r1[36], r2[36];
    int gid = blockIdx.x;          // hl*10 + g
    int l = gid / 20, rem = gid % 20, half = rem / 10, g = rem % 10;
    const float* p = lin + l * 63 + (half ? 29 : 0);
    float theta = p[g], phi = p[10 + g];
    float sp, cp; sincosf(phi, &sp, &cp);
    int tid = threadIdx.x;
    if (tid < 36) {
        int i1 = tid / 6, i2 = tid % 6;
        if (i1 + 1 < 6 && i2 - 1 >= 0) {
            float v = theta * sqrtf((float)((i1 + 1) * i2)) * (1.f / 64.f);
            h1[tid] = make_float2(v * cp, v * sp); r1[tid] = (i1 + 1) * 6 + (i2 - 1);
        } else { h1[tid] = make_float2(0.f, 0.f); r1[tid] = tid; }
        if (i1 - 1 >= 0 && i2 + 1 < 6) {
            float v = theta * sqrtf((float)(i1 * (i2 + 1))) * (1.f / 64.f);
            h2[tid] = make_float2(-v * cp, v * sp); r2[tid] = (i1 - 1) * 6 + (i2 + 1);
        } else { h2[tid] = make_float2(0.f, 0.f); r2[tid] = tid; }
    }
    for (int e = tid; e < 1296; e += blockDim.x) {
        int row = e / 36, col = e % 36;
        Rb[e] = make_float2((row == col) ? 1.f : 0.f, 0.f);
    }
    __syncthreads();
    for (int k = 16; k >= 1; k--) {
        for (int e = tid; e < 1296; e += blockDim.x) {
            int row = e / 36, col = e % 36;
            float2 acc = make_float2(0.f, 0.f);
            acc = cmadd(h1[row], Rb[r1[row] * 36 + col], acc);
            acc = cmadd(h2[row], Rb[r2[row] * 36 + col], acc);
            Tb[e] = acc;
        }
        __syncthreads();
        float inv = 1.f / (float)k;
        for (int e = tid; e < 1296; e += blockDim.x) {
            int row = e / 36, col = e % 36;
            float d = (row == col) ? 1.f : 0.f;
            Rb[e] = make_float2(fmaf(Tb[e].x, inv, d), Tb[e].y * inv);
        }
        __syncthreads();
    }
    float2* cur = Rb; float2* nxt = Tb;
    for (int s = 0; s < 6; s++) {
        for (int e = tid; e < 1296; e += blockDim.x) {
            int row = e / 36, col = e % 36;
            float2 acc = make_float2(0.f, 0.f);
#pragma unroll
            for (int kk = 0; kk < 36; kk++)
                acc = cmadd(cur[row * 36 + kk], cur[kk * 36 + col], acc);
            nxt[e] = acc;
        }
        __syncthreads();
        float2* t = cur; cur = nxt; nxt = t;
    }
    // write block-diagonal entries in padded-even-row layout (164 slots/gate)
    int hl = gid / 10, gg = gid % 10;
    for (int slot = tid; slot < 164; slot += blockDim.x) {
        int off = 0, s = 0, bsz = 1, bszP = 2;
        for (s = 0; s < 11; s++) {
            bsz = (s < 6) ? s + 1 : 11 - s;
            bszP = (bsz + 1) & ~1;
            if (slot < off + bsz * bszP) break;
            off += bsz * bszP;
        }
        int local = slot - off;
        int r = local / bszP, c = local % bszP;
        float2 v = make_float2(0.f, 0.f);
        if (c < bsz) {
            int lo = (s < 6) ? 0 : s - 5;
            int rj = (lo + r) * 6 + (s - lo - r);
            int cj = (lo + c) * 6 + (s - lo - c);
            v = cur[rj * 36 + cj];
        }
        g_all[hl * HLF2 + gg * 164 + slot] = v;
    }
}

// ---------------- BS apply: padded strides, conflict-tuned lane maps -----------
// per-K lane-dimension strides: base = d0*OM2 + d1*OM1 + d2*OM0
// K=0: others {m2,m3,m4}: (OM0,OM1,OM2)=(36,6,1)      residues (4,6,1) -> CF
// K=1: others {m0,m3,m4}: (1380,6,1)                  (4,6,1)          -> CF
// K=2: others {m0,m1,m4}: (1380,230,1)                (4,6,1)          -> CF
// K=3: others {m0,m1,m2}: (1380,36,230)  d0->m1!      (4,4,6)          -> 2-way
template <int K>
__device__ __forceinline__ void apply_bs_T(const float2* __restrict__ Uf, float2* st, int tid) {
    constexpr int SAv[4] = {P0, P1, P2, P3};
    constexpr int SBv[4] = {P1, P2, P3, P4};
    constexpr int OM0v[4] = {P2, P0, P0, P0};
    constexpr int OM1v[4] = {P3, P3, P1, P2};
    constexpr int OM2v[4] = {P4, P4, P4, P1};
    constexpr int SA = SAv[K], SB = SBv[K];
    constexpr int om0 = OM0v[K], om1 = OM1v[K], om2 = OM2v[K];
    if (tid >= 216) return;
    int d0 = tid % 6, t1 = tid / 6;
    int d1 = t1 % 6, d2 = t1 / 6;
    int base = d0 * om2 + d1 * om1 + d2 * om0;
    const ull* sp = (const ull*)st;
    const ulonglong2* Up = (const ulonglong2*)Uf;
    constexpr int secF4[11] = {0, 1, 3, 9, 17, 32, 50, 65, 73, 79, 81};
#pragma unroll
    for (int s = 0; s < 11; s++) {
        const int bsz = (s < 6) ? s + 1 : 11 - s;
        const int lo = (s < 6) ? 0 : s - 5;
        const int bszP2 = (bsz + 1) / 2;          // float4 per row
        ull dR[6], dI[6];
#pragma unroll
        for (int c = 0; c < bsz; c++) {
            ull v = sp[base + (lo + c) * SA + (s - lo - c) * SB];
            dupRI(v, dR[c], dI[c]);
        }
        if (bsz & 1) { dR[bsz] = 0; dI[bsz] = 0; }   // pad slot (coeff stored 0)
#pragma unroll
        for (int r = 0; r < bsz; r++) {
            ull S1 = 0, S2 = 0;
#pragma unroll
            for (int cp = 0; cp < bszP2; cp++) {
                ulonglong2 gg = Up[secF4[s] + r * bszP2 + cp];
                ffma2(S1, gg.x, dR[2 * cp]);     ffma2(S2, gg.x, dI[2 * cp]);
                ffma2(S1, gg.y, dR[2 * cp + 1]); ffma2(S2, gg.y, dI[2 * cp + 1]);
            }
            float2 f1 = *(float2*)&S1;
            float2 f2 = *(float2*)&S2;
            st[base + (lo + r) * SA + (s - lo - r) * SB] = make_float2(f1.x - f2.y, f1.y + f2.x);
        }
    }
}

// ---------------- 1-mode apply: tuned lane maps; M=4 vectorized ----------------
// base = e0*OM3 + e1*OM2 + e2*OM1 + e3*OM0
// M=0: (OM0..OM3) = (230,36,6,1)     CF
// M=1: (1380,36,6,1)                 CF
// M=2: (1380,230,6,1)                CF
// M=3: (1380,36,230,1)  e1->m1!      CF
// M=4: (1380,230,36,6)  + LDS.128 on contiguous q -> CF
template <int M, bool SQ>
__device__ __forceinline__ void apply_1m_T(const float2* __restrict__ Uf, float2* st, int tid) {
    constexpr int SMv[5] = {P0, P1, P2, P3, P4};
    constexpr int SM = SMv[M];
    constexpr int OM0v[5] = {P1, P0, P0, P0, P0};
    constexpr int OM1v[5] = {P2, P2, P1, P2, P1};
    constexpr int OM2v[5] = {P3, P3, P3, P1, P2};
    constexpr int OM3v[5] = {P4, P4, P4, P4, P3};
    constexpr int om0 = OM0v[M], om1 = OM1v[M], om2 = OM2v[M], om3 = OM3v[M];
    const ulonglong2* __restrict__ Up = (const ulonglong2*)Uf;
    for (int f = tid; f < 1296; f += BD) {
        int e0 = f % 6, t = f / 6;
        int e1 = t % 6; t /= 6;
        int e2 = t % 6; int e3 = t / 6;
        int base = e0 * om3 + e1 * om2 + e2 * om1 + e3 * om0;
        ull dR[6], dI[6];
        if (M == 4) {
            // contiguous q (stride 1), base even -> 3x LDS.128
            const float4* stv = (const float4*)(st + base);
            float4 v0 = stv[0], v1 = stv[1], v2 = stv[2];
            dup2f(v0.x, v0.y, dR[0], dI[0]); dup2f(v0.z, v0.w, dR[1], dI[1]);
            dup2f(v1.x, v1.y, dR[2], dI[2]); dup2f(v1.z, v1.w, dR[3], dI[3]);
            dup2f(v2.x, v2.y, dR[4], dI[4]); dup2f(v2.z, v2.w, dR[5], dI[5]);
        } else {
            const ull* sp = (const ull*)st;
#pragma unroll
            for (int q = 0; q < 6; q++) dupRI(sp[base + q * SM], dR[q], dI[q]);
        }
        float2 o[6];
#pragma unroll
        for (int p = 0; p < 6; p++) {
            ull S1 = 0, S2 = 0;
            if (SQ) {           // compact parity rows: q = (p&1)+2j, j<3, + zero pad
                const int q0 = p & 1;
                ulonglong2 g0 = Up[p * 2 + 0];
                ulonglong2 g1 = Up[p * 2 + 1];
                ffma2(S1, g0.x, dR[q0]);     ffma2(S2, g0.x, dI[q0]);
                ffma2(S1, g0.y, dR[q0 + 2]); ffma2(S2, g0.y, dI[q0 + 2]);
                ffma2(S1, g1.x, dR[q0 + 4]); ffma2(S2, g1.x, dI[q0 + 4]);
                ffma2(S1, g1.y, dR[q0]);     ffma2(S2, g1.y, dI[q0]);  // stored-zero pad
            } else {
#pragma unroll
                for (int cp = 0; cp < 3; cp++) {
                    ulonglong2 gg = Up[p * 3 + cp];
                    ffma2(S1, gg.x, dR[2 * cp]);     ffma2(S2, gg.x, dI[2 * cp]);
                    ffma2(S1, gg.y, dR[2 * cp + 1]); ffma2(S2, gg.y, dI[2 * cp + 1]);
                }
            }
            float2 f1 = *(float2*)&S1;
            float2 f2 = *(float2*)&S2;
            o[p] = make_float2(f1.x - f2.y, f1.y + f2.x);
        }
        if (M == 4) {
            float4* stv = (float4*)(st + base);
            stv[0] = make_float4(o[0].x, o[0].y, o[1].x, o[1].y);
            stv[1] = make_float4(o[2].x, o[2].y, o[3].x, o[3].y);
            stv[2] = make_float4(o[4].x, o[4].y, o[5].x, o[5].y);
        } else {
#pragma unroll
            for (int p = 0; p < 6; p++) st[base + p * SM] = o[p];
        }
    }
}

// ---------------- main kernel: one CTA per batch element, occ 2 ---------------
__global__ void __launch_bounds__(BD, 2) qdn_main(float* __restrict__ out) {
    extern __shared__ __align__(16) char smraw[];
    float2* Ustage = (float2*)smraw;                        // 14560 B
    float2* st = (float2*)(smraw + HLF2 * sizeof(float2));  // 66240 B (padded)
    __shared__ float ct[30];
    __shared__ float red[16];

    int b = blockIdx.x;
    int tid = threadIdx.x;

    // ---- initial product state (real) ----
    if (tid < 30) ct[tid] = g_init[(b * 5 + tid / 6) * 6 + (tid % 6)];
    __syncthreads();
    for (int idx = tid; idx < DIM; idx += BD) {
        int t = idx;
        int d4 = t % 6; t /= 6; int d3 = t % 6; t /= 6; int d2 = t % 6; t /= 6;
        int d1 = t % 6; int d0 = t / 6;
        int pos = d0 * P0 + d1 * P1 + d2 * P2 + d3 * P3 + d4;
        float v = ct[d0] * ct[6 + d1] * ct[12 + d2] * ct[18 + d3] * ct[24 + d4];
        st[pos] = make_float2(v, 0.f);
    }
    __syncthreads();

    for (int l = 0; l < 4; l++) {
        for (int half = 0; half < 2; half++) {
            // stage this half-layer's gates (float4 bulk copy)
            const float4* srcU = (const float4*)(g_all + (l * 2 + half) * HLF2);
            float4* dstU = (float4*)Ustage;
            for (int i = tid; i < HLF4; i += BD) dstU[i] = srcU[i];
            __syncthreads();
            // BS gate mode sequence: 0,2,1,3,0,2,1,3,0,2
            apply_bs_T<0>(Ustage + 0 * 164, st, tid); __syncthreads();
            apply_bs_T<2>(Ustage + 1 * 164, st, tid); __syncthreads();
            apply_bs_T<1>(Ustage + 2 * 164, st, tid); __syncthreads();
            apply_bs_T<3>(Ustage + 3 * 164, st, tid); __syncthreads();
            apply_bs_T<0>(Ustage + 4 * 164, st, tid); __syncthreads();
            apply_bs_T<2>(Ustage + 5 * 164, st, tid); __syncthreads();
            apply_bs_T<1>(Ustage + 6 * 164, st, tid); __syncthreads();
            apply_bs_T<3>(Ustage + 7 * 164, st, tid); __syncthreads();
            apply_bs_T<0>(Ustage + 8 * 164, st, tid); __syncthreads();
            apply_bs_T<2>(Ustage + 9 * 164, st, tid); __syncthreads();
            const float2* mg = Ustage + 1640;
            if (half == 0) {   // squeeze gates: compact parity rows
                apply_1m_T<0, true>(mg + 0 * 36, st, tid); __syncthreads();
                apply_1m_T<1, true>(mg + 1 * 36, st, tid); __syncthreads();
                apply_1m_T<2, true>(mg + 2 * 36, st, tid); __syncthreads();
                apply_1m_T<3, true>(mg + 3 * 36, st, tid); __syncthreads();
                apply_1m_T<4, true>(mg + 4 * 36, st, tid); __syncthreads();
            } else {           // displacement gates (rot+kerr folded): dense
                apply_1m_T<0, false>(mg + 0 * 36, st, tid); __syncthreads();
                apply_1m_T<1, false>(mg + 1 * 36, st, tid); __syncthreads();
                apply_1m_T<2, false>(mg + 2 * 36, st, tid); __syncthreads();
                apply_1m_T<3, false>(mg + 3 * 36, st, tid); __syncthreads();
                apply_1m_T<4, false>(mg + 4 * 36, st, tid); __syncthreads();
            }
        }
    }

    // ---- expectations <X_0>, <X_1> ----
    float acc0 = 0.f, acc1 = 0.f;
    for (int idx = tid; idx < DIM; idx += BD) {
        int t = idx;
        int d4 = t % 6; t /= 6; int d3 = t % 6; t /= 6; int d2 = t % 6; t /= 6;
        int d1 = t % 6; int d0 = t / 6;
        int pos = d0 * P0 + d1 * P1 + d2 * P2 + d3 * P3 + d4;
        float2 a = st[pos];
        if (d0 < 5) {
            float2 bb = st[pos + P0];
            acc0 = fmaf(SQT[d0], a.x * bb.x + a.y * bb.y, acc0);
        }
        if (d1 < 5) {
            float2 bb = st[pos + P1];
            acc1 = fmaf(SQT[d1], a.x * bb.x + a.y * bb.y, acc1);
        }
    }
#pragma unroll
    for (int off = 16; off > 0; off >>= 1) {
        acc0 += __shfl_down_sync(0xffffffffu, acc0, off);
        acc1 += __shfl_down_sync(0xffffffffu, acc1, off);
    }
    int w = tid >> 5, lane = tid & 31;
    if (lane == 0) { red[w] = acc0; red[8 + w] = acc1; }
    __syncthreads();
    if (tid == 0) {
        float s0 = 0.f, s1 = 0.f;
        for (int ww = 0; ww < 8; ww++) { s0 += red[ww]; s1 += red[8 + ww]; }
        out[b * 2 + 0] = 2.f * s0;
        out[b * 2 + 1] = 2.f * s1;
    }
}

// ---------------- launch ----------------
extern "C" void kernel_launch(void* const* d_in, const int* in_sizes, int n_in,
                              void* d_out, int out_size) {
    const float* x    = (const float*)d_in[0];
    const float* lin  = (const float*)d_in[1];
    const float* act  = (const float*)d_in[2];
    const float* lact = (const float*)d_in[3];
    float* out = (float*)d_out;
    int B = in_sizes[0] / 5;

    size_t shm = HLF2 * sizeof(float2) + (size_t)STATEF2 * sizeof(float2);   // 80800 B
    cudaFuncSetAttribute(qdn_main, cudaFuncAttributeMaxDynamicSharedMemorySize, (int)shm);

    int n1 = B * 5 + 40;
    noop_kernel<<<1, 32>>>();
    s1_kernel<<<(n1 + 255) / 256, 256>>>(x, lin, act, lact, B);
    s2_kernel<<<80, 256>>>(lin);
    qdn_main<<<B, BD, shm>>>(out);
}